// round 17
// baseline (speedup 1.0000x reference)
#include <cuda_runtime.h>
#include <cuda_fp16.h>
#include <cstdint>

#define L 2048
#define HID 4096
#define NH 32
#define NKV 8
#define HD 128
#define MAXP 4096

// ---------------------------------------------------------------------------
// PTX helpers (sm_80-class instructions only: valid on baseline sm_103 target)
// ---------------------------------------------------------------------------
__device__ __forceinline__ uint32_t smem_u32(const void* p) {
    uint32_t a;
    asm("{ .reg .u64 t; cvta.to.shared.u64 t, %1; cvt.u32.u64 %0, t; }" : "=r"(a) : "l"(p));
    return a;
}
__device__ __forceinline__ float fast_exp2(float x) {
    float y;
    asm("ex2.approx.f32 %0, %1;" : "=f"(y) : "f"(x));
    return y;
}
#define LDSM_X4(r0, r1, r2, r3, addr)                                              \
    asm volatile("ldmatrix.sync.aligned.m8n8.x4.shared.b16 {%0,%1,%2,%3}, [%4];"   \
                 : "=r"(r0), "=r"(r1), "=r"(r2), "=r"(r3) : "r"(addr))
#define LDSM_X4_T(r0, r1, r2, r3, addr)                                            \
    asm volatile("ldmatrix.sync.aligned.m8n8.x4.trans.shared.b16 {%0,%1,%2,%3}, [%4];" \
                 : "=r"(r0), "=r"(r1), "=r"(r2), "=r"(r3) : "r"(addr))
#define MMA_F16(d, a, b)                                                           \
    asm volatile("mma.sync.aligned.m16n8k16.row.col.f32.f16.f16.f32 "              \
                 "{%0,%1,%2,%3}, {%4,%5,%6,%7}, {%8,%9}, {%0,%1,%2,%3};"           \
                 : "+f"((d)[0]), "+f"((d)[1]), "+f"((d)[2]), "+f"((d)[3])          \
                 : "r"((a)[0]), "r"((a)[1]), "r"((a)[2]), "r"((a)[3]),             \
                   "r"((b)[0]), "r"((b)[1]))
#define CP_ASYNC16(dst, src)                                                       \
    asm volatile("cp.async.cg.shared.global [%0], [%1], 16;" :: "r"(dst), "l"(src))
#define CP_COMMIT() asm volatile("cp.async.commit_group;" ::: "memory")
#define CP_WAIT(n) asm volatile("cp.async.wait_group %0;" :: "n"(n) : "memory")

// ---------------------------------------------------------------------------
// scratch (device globals; no runtime alloc)
// ---------------------------------------------------------------------------
#define NW_TOTAL 41943040
#define OFF_WQ 0
#define OFF_WK 16777216
#define OFF_WV 20971520
#define OFF_WO 25165824

__device__ __half g_ha[(size_t)L * HID];      // rmsnorm out, single fp16
__device__ __half g_w[(size_t)NW_TOTAL];      // all weights, single fp16
__device__ __half g_aa[(size_t)L * HID];      // attn out, single fp16
__device__ __half g_qh[(size_t)L * HID];      // roped+scaled Q, single fp16
__device__ __half g_kh[(size_t)L * NKV * HD]; // roped K, single fp16
__device__ __half g_vb[(size_t)L * NKV * HD]; // V, single fp16 (GEMM epilogue)
__device__ float g_q[(size_t)L * HID];
__device__ float g_k[(size_t)L * NKV * HD];

__device__ __forceinline__ uint32_t pack_f16(float lo, float hi) {
    __half2 t = __floats2half2_rn(lo, hi);  // .x = lo bits [15:0]
    return *(uint32_t*)&t;
}

// ---------------------------------------------------------------------------
// cache copy — rows [L, MAXP) only; 4 float4 per thread (MLP=4)
// ---------------------------------------------------------------------------
__global__ void copy_caches_kernel(const float4* __restrict__ kin,
                                   const float4* __restrict__ vin,
                                   float4* __restrict__ kout,
                                   float4* __restrict__ vout) {
    int base = (blockIdx.x * 256 + threadIdx.x) * 4;
    const int n4 = (MAXP - L) * NKV * HD / 4;  // 524288, %4 == 0
    const int off = L * NKV * HD / 4;
    float4 v[4];
    if (base < n4) {
#pragma unroll
        for (int u = 0; u < 4; ++u) v[u] = kin[off + base + u];
#pragma unroll
        for (int u = 0; u < 4; ++u) kout[off + base + u] = v[u];
    } else {
        int b = base - n4;
#pragma unroll
        for (int u = 0; u < 4; ++u) v[u] = vin[off + b + u];
#pragma unroll
        for (int u = 0; u < 4; ++u) vout[off + b + u] = v[u];
    }
}

// ---------------------------------------------------------------------------
// fused weight convert: fp32 -> fp16; 4 float4 per thread (MLP=4)
// ---------------------------------------------------------------------------
__global__ void convert_all_kernel(const float4* __restrict__ wq,
                                   const float4* __restrict__ wk,
                                   const float4* __restrict__ wv,
                                   const float4* __restrict__ wo,
                                   __half* __restrict__ w) {
    int base = (blockIdx.x * 256 + threadIdx.x) * 4;  // float4 index
    // region boundaries (in float4 units) are all %4==0, so one region/thread
    const float4* src;
    int roff;
    if (base < OFF_WK / 4) { src = wq; roff = 0; }
    else if (base < OFF_WV / 4) { src = wk; roff = OFF_WK / 4; }
    else if (base < OFF_WO / 4) { src = wv; roff = OFF_WV / 4; }
    else { src = wo; roff = OFF_WO / 4; }
    float4 v[4];
#pragma unroll
    for (int u = 0; u < 4; ++u) v[u] = src[base - roff + u];
#pragma unroll
    for (int u = 0; u < 4; ++u) {
        __half2* hp = (__half2*)(w + (size_t)(base + u) * 4);
        hp[0] = __floats2half2_rn(v[u].x, v[u].y);
        hp[1] = __floats2half2_rn(v[u].z, v[u].w);
    }
}

// ---------------------------------------------------------------------------
// RMSNorm -> single fp16
// ---------------------------------------------------------------------------
__global__ void __launch_bounds__(256) rmsnorm_kernel(const float* __restrict__ x,
                                                      const float* __restrict__ w) {
    int row = blockIdx.x;
    const float* xr = x + (size_t)row * HID;
    int t = threadIdx.x;
    float vals[16];
    float local = 0.f;
#pragma unroll
    for (int i = 0; i < 16; ++i) {
        float v = xr[t + i * 256];
        vals[i] = v;
        local += v * v;
    }
    __shared__ float red[8];
#pragma unroll
    for (int o = 16; o; o >>= 1) local += __shfl_xor_sync(0xffffffffu, local, o);
    if ((t & 31) == 0) red[t >> 5] = local;
    __syncthreads();
    if (t < 8) {
        float v = red[t];
#pragma unroll
        for (int o = 4; o; o >>= 1) v += __shfl_xor_sync(0xffu, v, o);
        if (t == 0) red[0] = v;
    }
    __syncthreads();
    float rms = rsqrtf(red[0] / (float)HID + 1e-5f);
    size_t base = (size_t)row * HID;
#pragma unroll
    for (int i = 0; i < 16; ++i) {
        float y = vals[i] * rms * w[t + i * 256];
        g_ha[base + t + i * 256] = __float2half_rn(y);
    }
}

// ---------------------------------------------------------------------------
// fp16 single-term GEMM: C = A B^T (+res). CTA 128x128, 256 thr, 2 CTAs/SM.
// MODE 1: fused QKV (N=6144; q->C fp32, k->Ck fp32, v->Cvv fp32 + g_vb fp16).
// MODE 2: +res.
// ---------------------------------------------------------------------------
#define GSTRIDE 144
#define ATILE 18432            // 128 * 144
#define BOFF  18432
#define GSTAGE 36864
#define GEMM_SMEM (2 * GSTAGE) // 73728

template <int MODE>
__global__ void __launch_bounds__(256, 2) mma_gemm_kernel(
    const __half* __restrict__ A, const __half* __restrict__ B,
    float* __restrict__ C, float* __restrict__ Ck, float* __restrict__ Cvv,
    int N, const float* __restrict__ res) {
    extern __shared__ char sm[];
    const uint32_t sb = smem_u32(sm);
    const int tid = threadIdx.x;
    const int lane = tid & 31, w = tid >> 5;
    const int wm = w >> 2, wn = w & 3;          // 2 x 4 warps, warp tile 64x32
    const int bm = blockIdx.y * 128, bn = blockIdx.x * 128;

    float acc[4][4][4];
#pragma unroll
    for (int a = 0; a < 4; ++a)
#pragma unroll
        for (int b = 0; b < 4; ++b)
#pragma unroll
            for (int c = 0; c < 4; ++c) acc[a][b][c] = 0.f;

    auto issue = [&](int c, int s) {
#pragma unroll
        for (int j = 0; j < 4; ++j) {
            const int local = tid + j * 256;
            const int row = local >> 3;
            const int seg = local & 7;
            const void* g = A + (size_t)(bm + row) * HID + c * 64 + seg * 8;
            uint32_t dst = sb + s * GSTAGE + row * GSTRIDE + seg * 16;
            CP_ASYNC16(dst, g);
        }
#pragma unroll
        for (int j = 0; j < 4; ++j) {
            const int local = tid + j * 256;
            const int row = local >> 3;
            const int seg = local & 7;
            const void* g = B + (size_t)(bn + row) * HID + c * 64 + seg * 8;
            uint32_t dst = sb + s * GSTAGE + BOFF + row * GSTRIDE + seg * 16;
            CP_ASYNC16(dst, g);
        }
    };

    auto compute = [&](int s) {
        const uint32_t base = sb + s * GSTAGE;
        const int rsel = lane & 15;
        const int csel = (lane >> 4) << 4;
#pragma unroll
        for (int ks = 0; ks < 4; ++ks) {
            uint32_t a[4][4];
#pragma unroll
            for (int mt = 0; mt < 4; ++mt) {
                uint32_t ad = base + (wm * 64 + mt * 16 + rsel) * GSTRIDE + ks * 32 + csel;
                LDSM_X4(a[mt][0], a[mt][1], a[mt][2], a[mt][3], ad);
            }
            uint32_t b[4][2];
#pragma unroll
            for (int g = 0; g < 2; ++g) {
                uint32_t bd = base + BOFF + (wn * 32 + g * 16 + rsel) * GSTRIDE + ks * 32 + csel;
                uint32_t t0, t1, t2, t3;
                LDSM_X4(t0, t1, t2, t3, bd);
                b[2 * g][0] = t0; b[2 * g][1] = t2;
                b[2 * g + 1][0] = t1; b[2 * g + 1][1] = t3;
            }
#pragma unroll
            for (int nt = 0; nt < 4; ++nt)
#pragma unroll
                for (int mt = 0; mt < 4; ++mt)
                    MMA_F16(acc[mt][nt], a[mt], b[nt]);
        }
    };

    issue(0, 0); CP_COMMIT();
    issue(1, 1); CP_COMMIT();
#pragma unroll 1
    for (int c = 0; c < 64; ++c) {
        if (c + 1 < 64) { CP_WAIT(1); } else { CP_WAIT(0); }
        __syncthreads();
        compute(c & 1);
        if (c + 2 < 64) {
            __syncthreads();
            issue(c + 2, c & 1);
            CP_COMMIT();
        }
    }

    // epilogue: route output
    float* Cout = C;
    int ncols = N, bnl = bn;
    bool isV = false;
    if (MODE == 1) {
        if (bn < 4096) { Cout = C; ncols = 4096; bnl = bn; }
        else if (bn < 5120) { Cout = Ck; ncols = 1024; bnl = bn - 4096; }
        else { Cout = Cvv; ncols = 1024; bnl = bn - 5120; isV = true; }
    }
#pragma unroll
    for (int mt = 0; mt < 4; ++mt)
#pragma unroll
        for (int nt = 0; nt < 4; ++nt) {
            int row = bm + wm * 64 + mt * 16 + (lane >> 2);
            int col = bnl + wn * 32 + nt * 8 + ((lane & 3) << 1);
            size_t o0 = (size_t)row * ncols + col;
            size_t o1 = (size_t)(row + 8) * ncols + col;
            float2 v0 = make_float2(acc[mt][nt][0], acc[mt][nt][1]);
            float2 v1 = make_float2(acc[mt][nt][2], acc[mt][nt][3]);
            if (MODE == 2) {
                float2 r0 = *(const float2*)&res[o0];
                float2 r1 = *(const float2*)&res[o1];
                v0.x += r0.x; v0.y += r0.y;
                v1.x += r1.x; v1.y += r1.y;
            }
            *(float2*)&Cout[o0] = v0;
            *(float2*)&Cout[o1] = v1;
            if (MODE == 1 && isV) {  // V: also emit fp16 for flash
                *(__half2*)(g_vb + o0) = __floats2half2_rn(v0.x, v0.y);
                *(__half2*)(g_vb + o1) = __floats2half2_rn(v1.x, v1.y);
            }
        }
}

// ---------------------------------------------------------------------------
// fused RoPE: Q (scaled fp16) + K (fp16 + fp32 cache). V handled by GEMM.
// ---------------------------------------------------------------------------
#define QTOTAL (L * NH * 64)
#define KVTOTAL (L * NKV * 64)
__global__ void rope_all_kernel(const float* __restrict__ cosb, const float* __restrict__ sinb,
                                float* __restrict__ kc_out) {
    const float QS = 0.08838834764831845f * 1.4426950408889634f;
    int idx = blockIdx.x * 256 + threadIdx.x;
    if (idx < QTOTAL) {
        int d = idx & 63;
        int h = (idx >> 6) & (NH - 1);
        int i = idx >> 11;
        const float* qp = g_q + (size_t)i * HID + h * HD;
        float c0 = cosb[i * HD + d], s0 = sinb[i * HD + d];
        float c1 = cosb[i * HD + d + 64], s1 = sinb[i * HD + d + 64];
        float q0 = qp[d], q1 = qp[d + 64];
        size_t base = (size_t)i * HID + h * HD;
        g_qh[base + d] = __float2half_rn((q0 * c0 - q1 * s0) * QS);
        g_qh[base + d + 64] = __float2half_rn((q1 * c1 + q0 * s1) * QS);
    } else {
        idx -= QTOTAL;
        int d = idx & 63;
        int h = (idx >> 6) & (NKV - 1);
        int i = idx >> 9;
        size_t base = (size_t)i * (NKV * HD) + h * HD;
        float c0 = cosb[i * HD + d], s0 = sinb[i * HD + d];
        float c1 = cosb[i * HD + d + 64], s1 = sinb[i * HD + d + 64];
        float k0 = g_k[base + d], k1 = g_k[base + d + 64];
        float k0n = k0 * c0 - k1 * s0;
        float k1n = k1 * c1 + k0 * s1;
        kc_out[base + d] = k0n;
        kc_out[base + d + 64] = k1n;
        g_kh[base + d] = __float2half_rn(k0n);
        g_kh[base + d + 64] = __float2half_rn(k1n);
    }
}

// ---------------------------------------------------------------------------
// Flash attention via fp16 mma: BM=128 (8 warps x m16), BN=64, HD=128.
// PAIRED q-tiles: CTA (p, head) runs qt = NQT-1-p then qt = p — every CTA
// does exactly (NQT+1) kv-iterations total -> one balanced wave (256 CTAs,
// 2/SM). Double-buffered K/V with cross-iteration prefetch.
// ---------------------------------------------------------------------------
#define NQT (L / 128)          // 16
#define FSTRIDE 272
#define FQ 0
#define FK0 34816
#define FK1 52224
#define FV0 69632
#define FV1 87040
#define FLASH_SMEM 104448

__global__ void __launch_bounds__(256, 2) flash_kernel() {
    extern __shared__ char sm[];
    const uint32_t sb = smem_u32(sm);
    const int tid = threadIdx.x;
    const int lane = tid & 31, w = tid >> 5;
    const int head = blockIdx.y;
    const int kvh = head >> 2;
    const int rsel = lane & 15;
    const int csel = (lane >> 4) << 4;

    auto issue_kv = [&](int kt, int s) {
        const uint32_t kb = sb + (s ? FK1 : FK0);
        const uint32_t vb = sb + (s ? FV1 : FV0);
#pragma unroll
        for (int j = 0; j < 4; ++j) {
            const int local = tid + j * 256;
            const int row = local >> 4;
            const int seg = local & 15;
            size_t goff = (size_t)(kt * 64 + row) * (NKV * HD) + kvh * HD + seg * 8;
            CP_ASYNC16(kb + row * FSTRIDE + seg * 16, g_kh + goff);
        }
#pragma unroll
        for (int j = 0; j < 4; ++j) {
            const int local = tid + j * 256;
            const int row = local >> 4;
            const int seg = local & 15;
            size_t goff = (size_t)(kt * 64 + row) * (NKV * HD) + kvh * HD + seg * 8;
            CP_ASYNC16(vb + row * FSTRIDE + seg * 16, g_vb + goff);
        }
    };

#pragma unroll 1
    for (int half = 0; half < 2; ++half) {
        const int qt = half ? (int)blockIdx.x : (NQT - 1 - (int)blockIdx.x);
        __syncthreads();  // all warps done with smem from previous half

        // Q tile + first K/V tile
#pragma unroll
        for (int j = 0; j < 8; ++j) {
            const int local = tid + j * 256;
            const int row = local >> 4;
            const int seg = local & 15;
            const void* g = g_qh + (size_t)(qt * 128 + row) * HID + head * HD + seg * 8;
            CP_ASYNC16(sb + FQ + row * FSTRIDE + seg * 16, g);
        }
        issue_kv(0, 0);
        CP_COMMIT();

        float o_[16][4];
#pragma unroll
        for (int n = 0; n < 16; ++n)
#pragma unroll
            for (int c = 0; c < 4; ++c) o_[n][c] = 0.f;
        float m_[2] = {-1e30f, -1e30f};
        float l_[2] = {0.f, 0.f};

        const int kt_end = 2 * qt + 2;
#pragma unroll 1
        for (int kt = 0; kt < kt_end; ++kt) {
            const int s = kt & 1;
            CP_WAIT(0);
            __syncthreads();
            if (kt + 1 < kt_end) {
                issue_kv(kt + 1, s ^ 1);
                CP_COMMIT();
            }
            const uint32_t kb = sb + (s ? FK1 : FK0);
            const uint32_t vb = sb + (s ? FV1 : FV0);

            float sc[8][4];
#pragma unroll
            for (int n = 0; n < 8; ++n)
#pragma unroll
                for (int c = 0; c < 4; ++c) sc[n][c] = 0.f;
#pragma unroll
            for (int ks = 0; ks < 8; ++ks) {
                uint32_t a[4];
                uint32_t aaddr = sb + FQ + (w * 16 + rsel) * FSTRIDE + ks * 32 + csel;
                LDSM_X4(a[0], a[1], a[2], a[3], aaddr);
#pragma unroll
                for (int hf = 0; hf < 2; ++hf) {
                    uint32_t b[4][2];
#pragma unroll
                    for (int g = 0; g < 2; ++g) {
                        uint32_t bd = kb + ((hf * 2 + g) * 16 + rsel) * FSTRIDE + ks * 32 + csel;
                        uint32_t t0, t1, t2, t3;
                        LDSM_X4(t0, t1, t2, t3, bd);
                        b[2 * g][0] = t0; b[2 * g][1] = t2;
                        b[2 * g + 1][0] = t1; b[2 * g + 1][1] = t3;
                    }
#pragma unroll
                    for (int n = 0; n < 4; ++n) MMA_F16(sc[hf * 4 + n], a, b[n]);
                }
            }

            if (kt >= 2 * qt) {
                const int r0g = qt * 128 + w * 16 + (lane >> 2);
#pragma unroll
                for (int j = 0; j < 8; ++j) {
                    int cb = kt * 64 + j * 8 + ((lane & 3) << 1);
                    if (cb > r0g) sc[j][0] = -1e30f;
                    if (cb + 1 > r0g) sc[j][1] = -1e30f;
                    if (cb > r0g + 8) sc[j][2] = -1e30f;
                    if (cb + 1 > r0g + 8) sc[j][3] = -1e30f;
                }
            }

#pragma unroll
            for (int i = 0; i < 2; ++i) {
                float mt_ = -1e30f;
#pragma unroll
                for (int j = 0; j < 8; ++j)
                    mt_ = fmaxf(mt_, fmaxf(sc[j][2 * i], sc[j][2 * i + 1]));
                mt_ = fmaxf(mt_, __shfl_xor_sync(0xffffffffu, mt_, 1));
                mt_ = fmaxf(mt_, __shfl_xor_sync(0xffffffffu, mt_, 2));
                float mn = fmaxf(m_[i], mt_);
                float corr = fast_exp2(m_[i] - mn);
                m_[i] = mn;
                float rs = 0.f;
#pragma unroll
                for (int j = 0; j < 8; ++j) {
                    float p0 = fast_exp2(sc[j][2 * i] - mn);
                    float p1 = fast_exp2(sc[j][2 * i + 1] - mn);
                    sc[j][2 * i] = p0;
                    sc[j][2 * i + 1] = p1;
                    rs += p0 + p1;
                }
                rs += __shfl_xor_sync(0xffffffffu, rs, 1);
                rs += __shfl_xor_sync(0xffffffffu, rs, 2);
                l_[i] = l_[i] * corr + rs;
#pragma unroll
                for (int n = 0; n < 16; ++n) {
                    o_[n][2 * i] *= corr;
                    o_[n][2 * i + 1] *= corr;
                }
            }

            uint32_t pa[4][4];
#pragma unroll
            for (int t = 0; t < 4; ++t) {
                pa[t][0] = pack_f16(sc[2 * t][0], sc[2 * t][1]);
                pa[t][1] = pack_f16(sc[2 * t][2], sc[2 * t][3]);
                pa[t][2] = pack_f16(sc[2 * t + 1][0], sc[2 * t + 1][1]);
                pa[t][3] = pack_f16(sc[2 * t + 1][2], sc[2 * t + 1][3]);
            }

#pragma unroll
            for (int t = 0; t < 4; ++t) {
#pragma unroll
                for (int g = 0; g < 8; ++g) {
                    uint32_t vaddr = vb + (t * 16 + rsel) * FSTRIDE +
                                     (g * 16 + ((lane >> 4) << 3)) * 2;
                    uint32_t t0, t1, t2, t3;
                    LDSM_X4_T(t0, t1, t2, t3, vaddr);
                    uint32_t b0[2] = {t0, t1}, b1[2] = {t2, t3};
                    MMA_F16(o_[2 * g], pa[t], b0);
                    MMA_F16(o_[2 * g + 1], pa[t], b1);
                }
            }
        }

        // epilogue: normalize and emit single fp16 for the O projection
        const float inv0 = 1.f / l_[0];
        const float inv1 = 1.f / l_[1];
        const int r0g = qt * 128 + w * 16 + (lane >> 2);
#pragma unroll
        for (int nt = 0; nt < 16; ++nt) {
            int col = head * HD + nt * 8 + ((lane & 3) << 1);
            size_t o0 = (size_t)r0g * HID + col;
            size_t o1 = o0 + (size_t)8 * HID;
            *(__half2*)(g_aa + o0) = __floats2half2_rn(o_[nt][0] * inv0, o_[nt][1] * inv0);
            *(__half2*)(g_aa + o1) = __floats2half2_rn(o_[nt][2] * inv1, o_[nt][3] * inv1);
        }
    }
}

// ---------------------------------------------------------------------------
// launch
// ---------------------------------------------------------------------------
extern "C" void kernel_launch(void* const* d_in, const int* in_sizes, int n_in,
                              void* d_out, int out_size) {
    const float* x = (const float*)d_in[0];
    const float* cosb = (const float*)d_in[1];
    const float* sinb = (const float*)d_in[2];
    // d_in[3] position_ids (arange; not dereferenced), d_in[4] seq_len
    const float* kc_in = (const float*)d_in[5];
    const float* vc_in = (const float*)d_in[6];
    const float* lnw = (const float*)d_in[7];
    const float* Wq = (const float*)d_in[8];
    const float* Wk = (const float*)d_in[9];
    const float* Wv = (const float*)d_in[10];
    const float* Wo = (const float*)d_in[11];

    float* out = (float*)d_out;
    float* kc_out = out + (size_t)L * HID;
    float* vc_out = kc_out + (size_t)MAXP * NKV * HD;

    __half *pHa, *pW, *pAa;
    float *pQ, *pK;
    cudaGetSymbolAddress((void**)&pHa, g_ha);
    cudaGetSymbolAddress((void**)&pW, g_w);
    cudaGetSymbolAddress((void**)&pAa, g_aa);
    cudaGetSymbolAddress((void**)&pQ, g_q);
    cudaGetSymbolAddress((void**)&pK, g_k);

    copy_caches_kernel<<<(2 * (MAXP - L) * NKV * HD / 4) / (256 * 4), 256>>>(
        (const float4*)kc_in, (const float4*)vc_in, (float4*)kc_out, (float4*)vc_out);

    convert_all_kernel<<<(NW_TOTAL / 4) / (256 * 4), 256>>>(
        (const float4*)Wq, (const float4*)Wk, (const float4*)Wv, (const float4*)Wo, pW);

    rmsnorm_kernel<<<L, 256>>>(x, lnw);

    cudaFuncSetAttribute((const void*)mma_gemm_kernel<1>,
                         cudaFuncAttributeMaxDynamicSharedMemorySize, GEMM_SMEM);
    cudaFuncSetAttribute((const void*)mma_gemm_kernel<2>,
                         cudaFuncAttributeMaxDynamicSharedMemorySize, GEMM_SMEM);

    // fused Q+K+V projection; V epilogue writes vc_out fp32 + g_vb fp16
    mma_gemm_kernel<1><<<dim3(6144 / 128, L / 128), 256, GEMM_SMEM>>>(
        pHa, pW, pQ, pK, vc_out, 6144, nullptr);

    rope_all_kernel<<<(QTOTAL + KVTOTAL) / 256, 256>>>(cosb, sinb, kc_out);

    cudaFuncSetAttribute(flash_kernel, cudaFuncAttributeMaxDynamicSharedMemorySize, FLASH_SMEM);
    flash_kernel<<<dim3(NQT / 2, NH), 256, FLASH_SMEM>>>();

    // O projection with residual
    mma_gemm_kernel<2><<<dim3(HID / 128, L / 128), 256, GEMM_SMEM>>>(
        pAa, pW + OFF_WO, out, nullptr, nullptr, HID, x);
}